// round 14
// baseline (speedup 1.0000x reference)
#include <cuda_runtime.h>
#include <cuda_fp16.h>
#include <math.h>
#include <stdint.h>

// Shapes (fixed)
#define HW_DIM  1024
#define C_DIM   256
#define N_TOK   32768
#define K_CODES 1024
#define Z_ELEMS 8388608
#define BETA_F  0.25f

// tiling: CTA = 64 tokens x 1024 codes; 32 chunks of 32 codes; 2 CTAs/SM
#define MT      64
#define NCTA    (N_TOK / MT)     // 512
#define NCH     32
#define CHUNKS  (K_CODES / NCH)  // 32
#define KSTEPS  (C_DIM / 16)     // 16

// fp16 split scale (proven)
#define LO_S    2048.0f
#define LO_IS   4.8828125e-4f

// smem layout (bytes)
#define ROWB    528              // 264 halves (528%128=16, ldsm clean)
#define AH_OFF  0                // 64*528 = 33792
#define AL_OFF  33792            // -> 67584
#define BH_OFF  67584            // 32*528 = 16896 -> 84480
#define BL_OFF  84480            // -> 101376
#define NS_OFF  101376           // 32 floats -> 101504
#define CV_OFF  101504           // 64*2 floats -> 102016
#define CI_OFF  102016           // 64*2 ints  -> 102528
#define SMEM_TOTAL 102528        // x2 CTAs = 205056 <= 227KB

#define GL_BLOCKS 1024           // gather: 32 tokens/block, 8 threads/token

static __device__ int   g_idx[N_TOK];
static __device__ int   g_counts[K_CODES];
static __device__ float g_norms[K_CODES];
static __device__ float g_partials[GL_BLOCKS];
static __device__ int   g_done;

// ---------------------------------------------------------------------------
__device__ __forceinline__ uint32_t smem_u32(const void* p) {
    uint32_t a;
    asm("{ .reg .u64 T; cvta.to.shared.u64 T, %1; cvt.u32.u64 %0, T; }"
        : "=r"(a) : "l"(p));
    return a;
}
__device__ __forceinline__ void ldsm4(uint32_t addr, uint32_t r[4]) {
    asm volatile("ldmatrix.sync.aligned.m8n8.x4.shared.b16 {%0,%1,%2,%3}, [%4];"
                 : "=r"(r[0]), "=r"(r[1]), "=r"(r[2]), "=r"(r[3]) : "r"(addr));
}
__device__ __forceinline__ void mma_f16(float c[4], const uint32_t a[4],
                                        uint32_t b0, uint32_t b1) {
    asm volatile(
        "mma.sync.aligned.m16n8k16.row.col.f32.f16.f16.f32 "
        "{%0,%1,%2,%3}, {%4,%5,%6,%7}, {%8,%9}, {%0,%1,%2,%3};"
        : "+f"(c[0]), "+f"(c[1]), "+f"(c[2]), "+f"(c[3])
        : "r"(a[0]), "r"(a[1]), "r"(a[2]), "r"(a[3]), "r"(b0), "r"(b1));
}
__device__ __forceinline__ void split16(float a, __half& hi, __half& lo) {
    hi = __float2half_rn(a);
    lo = __float2half_rn((a - __half2float(hi)) * LO_S);
}

// ---------------------------------------------------------------------------
// prep: warp-per-code norms + zero counts + reset done counter
__global__ void prep_kernel(const float* __restrict__ cb) {
    const int code = blockIdx.x * 8 + (threadIdx.x >> 5);
    const int lane = threadIdx.x & 31;
    const float* row = cb + code * C_DIM;
    float s = 0.f;
    #pragma unroll
    for (int c = lane; c < C_DIM; c += 32) { float v = row[c]; s += v * v; }
    #pragma unroll
    for (int off = 16; off > 0; off >>= 1)
        s += __shfl_down_sync(0xffffffffu, s, off);
    if (lane == 0) {
        g_norms[code]  = s;
        g_counts[code] = 0;
        if (code == 0) g_done = 0;
    }
}

// ---------------------------------------------------------------------------
// split-fp16 GEMM-argmin, 2 CTAs/SM for cross-CTA staging/MMA overlap.
// 8 warps = 4 token-groups(16 tok) x 2 code-groups(16 codes).
__global__ __launch_bounds__(256, 2)
void argmin_kernel(const float* __restrict__ z, const float* __restrict__ cb) {
    extern __shared__ char smem[];
    const uint32_t sb = smem_u32(smem);
    float* ns    = (float*)(smem + NS_OFF);
    float* candv = (float*)(smem + CV_OFF);
    int*   candi = (int*)(smem + CI_OFF);

    const int tid  = threadIdx.x;
    const int warp = tid >> 5;
    const int lane = tid & 31;
    const int tg   = warp & 3;       // token group (16 tokens)
    const int cg   = warp >> 2;      // 16-code half of 32-chunk
    const int g    = lane >> 2;
    const int t    = lane & 3;
    const int l15  = lane & 15;

    const int n0  = blockIdx.x * MT;
    const int b   = n0 >> 10;
    const int hw0 = n0 & 1023;
    const float* zb = z + (size_t)b * (C_DIM * HW_DIM) + hw0;
    const float4* cb4 = (const float4*)cb;

    // stage A (64 tok x 256 c) as fp16 hi/lo, coalesced over tokens
    #pragma unroll 4
    for (int it = 0; it < 64; it++) {
        int i  = it * 256 + tid;
        int tk = i & 63;
        int c  = i >> 6;
        float a = zb[(size_t)c * HW_DIM + tk];
        __half hi, lo;
        split16(a, hi, lo);
        *(__half*)(smem + AH_OFF + tk * ROWB + c * 2) = hi;
        *(__half*)(smem + AL_OFF + tk * ROWB + c * 2) = lo;
    }

    // per-lane ldsm addresses
    const uint32_t aH = sb + AH_OFF
        + (uint32_t)((tg * 16 + l15) * ROWB + (lane >> 4) * 16);
    const uint32_t aL = aH + (uint32_t)(AL_OFF - AH_OFF);
    // B x4: m0=codes0-7/k0-7, m1=codes0-7/k8-15, m2=codes8-15/k0-7, m3=codes8-15/k8-15
    const int bRow = cg * 16 + ((lane & 16) >> 1) + (lane & 7);
    const int bK   = (lane >> 3) & 1;
    const uint32_t bHb = sb + BH_OFF + (uint32_t)(bRow * ROWB + bK * 16);
    const uint32_t bLb = bHb + (uint32_t)(BL_OFF - BH_OFF);

    float bestv[2];
    int   besti[2];
    #pragma unroll
    for (int s = 0; s < 2; s++) { bestv[s] = 3.4e38f; besti[s] = 0; }

    for (int ch = 0; ch < CHUNKS; ch++) {
        const int k0c = ch * NCH;
        __syncthreads();   // protect B from previous chunk's readers
        // stage B chunk (32 codes x 256 c) fp16 hi/lo
        #pragma unroll
        for (int it = 0; it < 8; it++) {
            int i    = it * 256 + tid;
            int code = i >> 6;
            int j4   = i & 63;
            float4 v = cb4[(size_t)(k0c + code) * 64 + j4];
            __half h0, l0, h1, l1, h2, l2, h3, l3;
            split16(v.x, h0, l0); split16(v.y, h1, l1);
            split16(v.z, h2, l2); split16(v.w, h3, l3);
            __half2 hA = __halves2half2(h0, h1), hB = __halves2half2(h2, h3);
            __half2 lA = __halves2half2(l0, l1), lB = __halves2half2(l2, l3);
            uint32_t off = (uint32_t)(code * ROWB + j4 * 8);
            *(uint2*)(smem + BH_OFF + off) = make_uint2(*(uint32_t*)&hA, *(uint32_t*)&hB);
            *(uint2*)(smem + BL_OFF + off) = make_uint2(*(uint32_t*)&lA, *(uint32_t*)&lB);
        }
        if (tid < NCH) ns[tid] = g_norms[k0c + tid];
        __syncthreads();

        float hh[2][4], md[2][4];
        #pragma unroll
        for (int nb = 0; nb < 2; nb++)
            #pragma unroll
            for (int q = 0; q < 4; q++) { hh[nb][q] = 0.f; md[nb][q] = 0.f; }

        #pragma unroll 4
        for (int ks = 0; ks < KSTEPS; ks++) {
            uint32_t ah[4], al[4], bh[4], bl[4];
            ldsm4(aH + (uint32_t)(ks * 32), ah);
            ldsm4(aL + (uint32_t)(ks * 32), al);
            ldsm4(bHb + (uint32_t)(ks * 32), bh);
            ldsm4(bLb + (uint32_t)(ks * 32), bl);
            #pragma unroll
            for (int nb = 0; nb < 2; nb++) {
                mma_f16(hh[nb], ah, bh[nb * 2], bh[nb * 2 + 1]);
                mma_f16(md[nb], ah, bl[nb * 2], bl[nb * 2 + 1]);
                mma_f16(md[nb], al, bh[nb * 2], bh[nb * 2 + 1]);
            }
        }

        // epilogue: dist = |e|^2 - 2 (hh + md/2048)
        #pragma unroll
        for (int nb = 0; nb < 2; nb++) {
            int cl = cg * 16 + nb * 8 + 2 * t;
            float nk0 = ns[cl];
            float nk1 = ns[cl + 1];
            int code0 = k0c + cl;
            float d00 = nk0 - 2.f * (hh[nb][0] + md[nb][0] * LO_IS);
            float d01 = nk1 - 2.f * (hh[nb][1] + md[nb][1] * LO_IS);
            float d10 = nk0 - 2.f * (hh[nb][2] + md[nb][2] * LO_IS);
            float d11 = nk1 - 2.f * (hh[nb][3] + md[nb][3] * LO_IS);
            if (d00 < bestv[0]) { bestv[0] = d00; besti[0] = code0; }
            if (d01 < bestv[0]) { bestv[0] = d01; besti[0] = code0 + 1; }
            if (d10 < bestv[1]) { bestv[1] = d10; besti[1] = code0; }
            if (d11 < bestv[1]) { bestv[1] = d11; besti[1] = code0 + 1; }
        }
    }

    // lane-reduce across t (lanes 4g..4g+3 share a token row)
    #pragma unroll
    for (int s = 0; s < 2; s++) {
        #pragma unroll
        for (int m = 1; m <= 2; m <<= 1) {
            float v2 = __shfl_xor_sync(0xffffffffu, bestv[s], m);
            int   i2 = __shfl_xor_sync(0xffffffffu, besti[s], m);
            if (v2 < bestv[s] || (v2 == bestv[s] && i2 < besti[s])) {
                bestv[s] = v2; besti[s] = i2;
            }
        }
    }
    if (t == 0) {
        #pragma unroll
        for (int s = 0; s < 2; s++) {
            int tok = tg * 16 + s * 8 + g;
            candv[tok * 2 + cg] = bestv[s];
            candi[tok * 2 + cg] = besti[s];
        }
    }
    __syncthreads();
    if (tid < MT) {
        float v0 = candv[tid * 2], v1 = candv[tid * 2 + 1];
        int   i0 = candi[tid * 2], i1 = candi[tid * 2 + 1];
        int bi;
        if (v1 < v0 || (v1 == v0 && i1 < i0)) bi = i1; else bi = i0;
        g_idx[n0 + tid] = bi;
        atomicAdd(&g_counts[bi], 1);
    }
}

// ---------------------------------------------------------------------------
// gather + fused finalize: 1024 blocks, 32 tokens/block, 8 threads/token.
__global__ __launch_bounds__(256)
void gather_loss_kernel(const float* __restrict__ z,
                        const float* __restrict__ cb,
                        float* __restrict__ out, int out_size) {
    __shared__ float red[256];
    __shared__ float red2[256];
    __shared__ bool  amLast;
    const int tid = threadIdx.x;
    const int tok = blockIdx.x * 32 + (tid & 31);
    const int cc  = tid >> 5;
    const int k   = g_idx[tok];
    const int b   = tok >> 10;
    const int hw  = tok & 1023;
    const float4* c4p = (const float4*)cb + (size_t)k * 64 + cc * 8;
    const size_t base = (size_t)b * (C_DIM * HW_DIM) + (size_t)cc * 32 * HW_DIM + hw;
    const float* zp = z + base;
    float* op = out + base;
    float s = 0.f;
    #pragma unroll
    for (int j = 0; j < 8; j++) {
        float4 e = c4p[j];
        int c = j * 4;
        float d0 = e.x - zp[(c + 0) * HW_DIM];
        float d1 = e.y - zp[(c + 1) * HW_DIM];
        float d2 = e.z - zp[(c + 2) * HW_DIM];
        float d3 = e.w - zp[(c + 3) * HW_DIM];
        s += d0 * d0 + d1 * d1 + d2 * d2 + d3 * d3;
        op[(c + 0) * HW_DIM] = e.x;
        op[(c + 1) * HW_DIM] = e.y;
        op[(c + 2) * HW_DIM] = e.z;
        op[(c + 3) * HW_DIM] = e.w;
    }
    red[tid] = s;
    __syncthreads();
    for (int off = 128; off > 0; off >>= 1) {
        if (tid < off) red[tid] += red[tid + off];
        __syncthreads();
    }
    if (tid == 0) {
        g_partials[blockIdx.x] = red[0];
        __threadfence();
        amLast = (atomicAdd(&g_done, 1) == GL_BLOCKS - 1);
    }
    __syncthreads();

    if (amLast) {
        float ls = g_partials[tid] + g_partials[tid + 256]
                 + g_partials[tid + 512] + g_partials[tid + 768];
        float en = 0.f;
        #pragma unroll
        for (int j = 0; j < 4; j++) {
            float p  = (float)g_counts[tid * 4 + j] * (1.0f / (float)N_TOK);
            float pc = fmaxf(p, 1e-10f);
            en += pc * logf(pc);
        }
        red[tid]  = ls;
        red2[tid] = en;
        __syncthreads();
        for (int off = 128; off > 0; off >>= 1) {
            if (tid < off) { red[tid] += red[tid + off]; red2[tid] += red2[tid + off]; }
            __syncthreads();
        }
        if (tid == 0) {
            float mse = red[0] * (1.0f / (float)Z_ELEMS);
            if (out_size >= Z_ELEMS + 1) out[Z_ELEMS]     = mse * (1.0f + BETA_F);
            if (out_size >= Z_ELEMS + 2) out[Z_ELEMS + 1] = expf(-red2[0]);
        }
    }
}

// ---------------------------------------------------------------------------
extern "C" void kernel_launch(void* const* d_in, const int* in_sizes, int n_in,
                              void* d_out, int out_size) {
    const float* z  = (const float*)d_in[0];
    const float* cb = (const float*)d_in[1];
    float* out = (float*)d_out;

    cudaFuncSetAttribute(argmin_kernel,
                         cudaFuncAttributeMaxDynamicSharedMemorySize, SMEM_TOTAL);

    prep_kernel<<<K_CODES / 8, 256>>>(cb);
    argmin_kernel<<<NCTA, 256, SMEM_TOTAL>>>(z, cb);
    gather_loss_kernel<<<GL_BLOCKS, 256>>>(z, cb, out, out_size);
}

// round 15
// speedup vs baseline: 1.0350x; 1.0350x over previous
#include <cuda_runtime.h>
#include <cuda_fp16.h>
#include <math.h>
#include <stdint.h>

// Shapes (fixed)
#define HW_DIM  1024
#define C_DIM   256
#define N_TOK   32768
#define K_CODES 1024
#define Z_ELEMS 8388608
#define BETA_F  0.25f

// tiling: CTA = 128 threads, 64 tokens x 1024 codes; 64 chunks of 16 codes
#define MT      64
#define NCTA    (N_TOK / MT)     // 512
#define NCH     16
#define CHUNKS  (K_CODES / NCH)  // 64
#define KSTEPS  (C_DIM / 16)     // 16

// smem layout (bytes)
#define ROWB    528              // A rows: 264 halves (528%128=16, ldsm clean)
#define AH_OFF  0                // 64*528 = 33792
#define AL_OFF  33792            // -> 67584
#define RING_OFF 67584           // 2 slots x 16384 (16 codes x 1024B swizzled)
#define RSLOT   16384
#define NS_OFF  100352           // 1024 floats -> 104448
#define SMEM_TOTAL 104448        // x2 CTAs = 208896 <= 227KB

#define GL_BLOCKS 1024           // gather: 32 tokens/block, 8 threads/token

static __device__ int    g_idx[N_TOK];
static __device__ int    g_counts[K_CODES];
static __device__ float  g_norms[K_CODES];
static __device__ float  g_partials[GL_BLOCKS];
static __device__ int    g_done;
// pre-split codebook: row = 1024B = 32 k-blocks of [hi x8 | lo x8] halves
static __device__ __half g_cbi[K_CODES * 512];

// ---------------------------------------------------------------------------
__device__ __forceinline__ uint32_t smem_u32(const void* p) {
    uint32_t a;
    asm("{ .reg .u64 T; cvta.to.shared.u64 T, %1; cvt.u32.u64 %0, T; }"
        : "=r"(a) : "l"(p));
    return a;
}
__device__ __forceinline__ void ldsm4(uint32_t addr, uint32_t r[4]) {
    asm volatile("ldmatrix.sync.aligned.m8n8.x4.shared.b16 {%0,%1,%2,%3}, [%4];"
                 : "=r"(r[0]), "=r"(r[1]), "=r"(r[2]), "=r"(r[3]) : "r"(addr));
}
__device__ __forceinline__ void mma_f16(float c[4], const uint32_t a[4],
                                        uint32_t b0, uint32_t b1) {
    asm volatile(
        "mma.sync.aligned.m16n8k16.row.col.f32.f16.f16.f32 "
        "{%0,%1,%2,%3}, {%4,%5,%6,%7}, {%8,%9}, {%0,%1,%2,%3};"
        : "+f"(c[0]), "+f"(c[1]), "+f"(c[2]), "+f"(c[3])
        : "r"(a[0]), "r"(a[1]), "r"(a[2]), "r"(a[3]), "r"(b0), "r"(b1));
}
#define CP_ASYNC16(dst, src) \
    asm volatile("cp.async.cg.shared.global [%0], [%1], 16;" :: "r"(dst), "l"(src))
#define CP_COMMIT() asm volatile("cp.async.commit_group;" ::: "memory")
#define CP_WAIT1()  asm volatile("cp.async.wait_group 1;" ::: "memory")
#define CP_WAIT0()  asm volatile("cp.async.wait_group 0;" ::: "memory")

// ---------------------------------------------------------------------------
// prep: interleaved hi/lo codebook (unscaled residual) + norms + zero state
__global__ void prep_kernel(const float* __restrict__ cb) {
    __shared__ float red[8];
    const int code = blockIdx.x;
    const int c    = threadIdx.x;
    float v = cb[code * C_DIM + c];
    __half hi = __float2half_rn(v);
    __half lo = __float2half_rn(v - __half2float(hi));
    int base = code * 512 + (c >> 3) * 16 + (c & 7);
    g_cbi[base]     = hi;
    g_cbi[base + 8] = lo;
    float s = v * v;
    #pragma unroll
    for (int off = 16; off > 0; off >>= 1)
        s += __shfl_down_sync(0xffffffffu, s, off);
    if ((c & 31) == 0) red[c >> 5] = s;
    __syncthreads();
    if (c == 0) {
        float t = 0.f;
        #pragma unroll
        for (int i = 0; i < 8; i++) t += red[i];
        g_norms[code]  = t;
        g_counts[code] = 0;
        if (code == 0) g_done = 0;
    }
}

// ---------------------------------------------------------------------------
// split-fp16 GEMM-argmin: 128 threads (4 warps), 2 CTAs/SM, cp.async B ring.
// Each warp: 16 tokens x all codes; per-token argmin completes in-warp.
__global__ __launch_bounds__(128, 2)
void argmin_kernel(const float* __restrict__ z) {
    extern __shared__ char smem[];
    const uint32_t sb = smem_u32(smem);
    float* ns = (float*)(smem + NS_OFF);

    const int tid  = threadIdx.x;
    const int warp = tid >> 5;       // token group: 16 tokens
    const int lane = tid & 31;
    const int g    = lane >> 2;
    const int t    = lane & 3;
    const int l15  = lane & 15;

    const int n0  = blockIdx.x * MT;
    const int b   = n0 >> 10;
    const int hw0 = n0 & 1023;
    const float* zb = z + (size_t)b * (C_DIM * HW_DIM) + hw0;

    // ---- B prefetch: chunk = 16 codes x 1024B rows, XOR-swizzled ----------
    auto prefetch = [&](int p) {
        const char* src = (const char*)g_cbi + (size_t)p * RSLOT;
        uint32_t dst0 = sb + RING_OFF + (uint32_t)((p & 1) * RSLOT);
        #pragma unroll
        for (int it = 0; it < 8; it++) {
            int i    = it * 128 + tid;       // 0..1023
            int code = i >> 6;
            int seg  = i & 63;
            uint32_t dst = dst0 + (uint32_t)(code * 1024 + ((seg ^ (code & 7)) << 4));
            CP_ASYNC16(dst, src + (size_t)i * 16);
        }
    };
    prefetch(0); CP_COMMIT();
    prefetch(1); CP_COMMIT();

    // ---- stage A (64 tok x 256 c) as fp16 hi/lo (unscaled residual) -------
    #pragma unroll 4
    for (int it = 0; it < 128; it++) {
        int i  = it * 128 + tid;
        int tk = i & 63;
        int c  = i >> 6;
        float a = zb[(size_t)c * HW_DIM + tk];
        __half hi = __float2half_rn(a);
        __half lo = __float2half_rn(a - __half2float(hi));
        *(__half*)(smem + AH_OFF + tk * ROWB + c * 2) = hi;
        *(__half*)(smem + AL_OFF + tk * ROWB + c * 2) = lo;
    }
    #pragma unroll
    for (int it = 0; it < 8; it++) ns[it * 128 + tid] = g_norms[it * 128 + tid];

    // per-lane ldsm addresses
    const uint32_t aH = sb + AH_OFF
        + (uint32_t)((warp * 16 + l15) * ROWB + (lane >> 4) * 16);
    const uint32_t aL = aH + (uint32_t)(AL_OFF - AH_OFF);
    const int bcode = lane & 7;
    const int bgrp  = lane >> 3;     // 0..3: selects [hi k0-7][lo k0-7][hi k8-15][lo k8-15]
    const uint32_t brow0 = (uint32_t)(bcode * 1024);
    const uint32_t brow1 = (uint32_t)((8 + bcode) * 1024);

    float bestv[2];
    int   besti[2];
    #pragma unroll
    for (int s = 0; s < 2; s++) { bestv[s] = 3.4e38f; besti[s] = 0; }

    for (int ch = 0; ch < CHUNKS; ch++) {
        if (ch == CHUNKS - 1) CP_WAIT0(); else CP_WAIT1();
        __syncthreads();             // slot data + (ch==0) A staging visible

        const uint32_t pbase = sb + RING_OFF + (uint32_t)((ch & 1) * RSLOT);

        float hh[2][4], md[2][4];
        #pragma unroll
        for (int nb = 0; nb < 2; nb++)
            #pragma unroll
            for (int q = 0; q < 4; q++) { hh[nb][q] = 0.f; md[nb][q] = 0.f; }

        #pragma unroll 4
        for (int ks = 0; ks < KSTEPS; ks++) {
            uint32_t ah[4], al[4], b0[4], b1[4];
            ldsm4(aH + (uint32_t)(ks * 32), ah);
            ldsm4(aL + (uint32_t)(ks * 32), al);
            const uint32_t koff = (uint32_t)(((4 * ks + bgrp) ^ bcode) << 4);
            ldsm4(pbase + brow0 + koff, b0);   // codes 0-7
            ldsm4(pbase + brow1 + koff, b1);   // codes 8-15
            mma_f16(hh[0], ah, b0[0], b0[2]);
            mma_f16(md[0], ah, b0[1], b0[3]);
            mma_f16(md[0], al, b0[0], b0[2]);
            mma_f16(hh[1], ah, b1[0], b1[2]);
            mma_f16(md[1], ah, b1[1], b1[3]);
            mma_f16(md[1], al, b1[0], b1[2]);
        }

        __syncthreads();             // all warps done reading slot
        if (ch + 2 < CHUNKS) { prefetch(ch + 2); CP_COMMIT(); }

        // epilogue: dist = |e|^2 - 2*hh - 2*md
        #pragma unroll
        for (int nb = 0; nb < 2; nb++) {
            int code0 = ch * NCH + nb * 8 + 2 * t;
            float nk0 = ns[code0];
            float nk1 = ns[code0 + 1];
            float d00 = nk0 - 2.f * hh[nb][0] - 2.f * md[nb][0];
            float d01 = nk1 - 2.f * hh[nb][1] - 2.f * md[nb][1];
            float d10 = nk0 - 2.f * hh[nb][2] - 2.f * md[nb][2];
            float d11 = nk1 - 2.f * hh[nb][3] - 2.f * md[nb][3];
            if (d00 < bestv[0]) { bestv[0] = d00; besti[0] = code0; }
            if (d01 < bestv[0]) { bestv[0] = d01; besti[0] = code0 + 1; }
            if (d10 < bestv[1]) { bestv[1] = d10; besti[1] = code0; }
            if (d11 < bestv[1]) { bestv[1] = d11; besti[1] = code0 + 1; }
        }
    }

    // lane-reduce across t (lanes 4g..4g+3 share a token row); in-warp final
    #pragma unroll
    for (int s = 0; s < 2; s++) {
        #pragma unroll
        for (int m = 1; m <= 2; m <<= 1) {
            float v2 = __shfl_xor_sync(0xffffffffu, bestv[s], m);
            int   i2 = __shfl_xor_sync(0xffffffffu, besti[s], m);
            if (v2 < bestv[s] || (v2 == bestv[s] && i2 < besti[s])) {
                bestv[s] = v2; besti[s] = i2;
            }
        }
    }
    if (t == 0) {
        #pragma unroll
        for (int s = 0; s < 2; s++) {
            int tok = warp * 16 + s * 8 + g;
            g_idx[n0 + tok] = besti[s];
            atomicAdd(&g_counts[besti[s]], 1);
        }
    }
}

// ---------------------------------------------------------------------------
// gather + fused finalize: 1024 blocks, 32 tokens/block, 8 threads/token.
__global__ __launch_bounds__(256)
void gather_loss_kernel(const float* __restrict__ z,
                        const float* __restrict__ cb,
                        float* __restrict__ out, int out_size) {
    __shared__ float red[256];
    __shared__ float red2[256];
    __shared__ bool  amLast;
    const int tid = threadIdx.x;
    const int tok = blockIdx.x * 32 + (tid & 31);
    const int cc  = tid >> 5;
    const int k   = g_idx[tok];
    const int b   = tok >> 10;
    const int hw  = tok & 1023;
    const float4* c4p = (const float4*)cb + (size_t)k * 64 + cc * 8;
    const size_t base = (size_t)b * (C_DIM * HW_DIM) + (size_t)cc * 32 * HW_DIM + hw;
    const float* zp = z + base;
    float* op = out + base;
    float s = 0.f;
    #pragma unroll
    for (int j = 0; j < 8; j++) {
        float4 e = c4p[j];
        int c = j * 4;
        float d0 = e.x - zp[(c + 0) * HW_DIM];
        float d1 = e.y - zp[(c + 1) * HW_DIM];
        float d2 = e.z - zp[(c + 2) * HW_DIM];
        float d3 = e.w - zp[(c + 3) * HW_DIM];
        s += d0 * d0 + d1 * d1 + d2 * d2 + d3 * d3;
        op[(c + 0) * HW_DIM] = e.x;
        op[(c + 1) * HW_DIM] = e.y;
        op[(c + 2) * HW_DIM] = e.z;
        op[(c + 3) * HW_DIM] = e.w;
    }
    red[tid] = s;
    __syncthreads();
    for (int off = 128; off > 0; off >>= 1) {
        if (tid < off) red[tid] += red[tid + off];
        __syncthreads();
    }
    if (tid == 0) {
        g_partials[blockIdx.x] = red[0];
        __threadfence();
        amLast = (atomicAdd(&g_done, 1) == GL_BLOCKS - 1);
    }
    __syncthreads();

    if (amLast) {
        float ls = g_partials[tid] + g_partials[tid + 256]
                 + g_partials[tid + 512] + g_partials[tid + 768];
        float en = 0.f;
        #pragma unroll
        for (int j = 0; j < 4; j++) {
            float p  = (float)g_counts[tid * 4 + j] * (1.0f / (float)N_TOK);
            float pc = fmaxf(p, 1e-10f);
            en += pc * logf(pc);
        }
        red[tid]  = ls;
        red2[tid] = en;
        __syncthreads();
        for (int off = 128; off > 0; off >>= 1) {
            if (tid < off) { red[tid] += red[tid + off]; red2[tid] += red2[tid + off]; }
            __syncthreads();
        }
        if (tid == 0) {
            float mse = red[0] * (1.0f / (float)Z_ELEMS);
            if (out_size >= Z_ELEMS + 1) out[Z_ELEMS]     = mse * (1.0f + BETA_F);
            if (out_size >= Z_ELEMS + 2) out[Z_ELEMS + 1] = expf(-red2[0]);
        }
    }
}

// ---------------------------------------------------------------------------
extern "C" void kernel_launch(void* const* d_in, const int* in_sizes, int n_in,
                              void* d_out, int out_size) {
    const float* z  = (const float*)d_in[0];
    const float* cb = (const float*)d_in[1];
    float* out = (float*)d_out;

    cudaFuncSetAttribute(argmin_kernel,
                         cudaFuncAttributeMaxDynamicSharedMemorySize, SMEM_TOTAL);

    prep_kernel<<<K_CODES, 256>>>(cb);
    argmin_kernel<<<NCTA, 128, SMEM_TOTAL>>>(z);
    gather_loss_kernel<<<GL_BLOCKS, 256>>>(z, cb, out, out_size);
}

// round 16
// speedup vs baseline: 1.1341x; 1.0957x over previous
#include <cuda_runtime.h>
#include <cuda_fp16.h>
#include <math.h>
#include <stdint.h>

// Shapes (fixed)
#define HW_DIM  1024
#define C_DIM   256
#define N_TOK   32768
#define K_CODES 1024
#define Z_ELEMS 8388608
#define BETA_F  0.25f

// tiling (R4/R12-identical)
#define MT      128            // tokens per CTA
#define NCH     64             // codes per chunk
#define CHUNKS  (K_CODES / NCH)
#define KSTEPS  (C_DIM / 16)   // 16

// fp16 split scale (proven)
#define LO_S    2048.0f
#define LO_IS   4.8828125e-4f

// smem layout (bytes)
#define ROWB    528             // A rows: 264 halves (528%128=16, ldsm clean)
#define AH_OFF  0               // 128*528 = 67584
#define AL_OFF  67584           // -> 135168
#define BI_OFF  135168          // B interleaved: 64 codes x 1024B = 65536 -> 200704
#define NS_OFF  200704          // 64 floats -> 200960
#define CV_OFF  200960          // 128*2 floats -> 201984
#define CI_OFF  201984          // 128*2 ints -> 203008
#define SMEM_TOTAL 203008

#define GL_BLOCKS 1024          // gather: 32 tokens/block, 8 threads/token

static __device__ int   g_idx[N_TOK];
static __device__ int   g_counts[K_CODES];
static __device__ float g_norms[K_CODES];
static __device__ float g_partials[GL_BLOCKS];
static __device__ int   g_done;

// ---------------------------------------------------------------------------
__device__ __forceinline__ uint32_t smem_u32(const void* p) {
    uint32_t a;
    asm("{ .reg .u64 T; cvta.to.shared.u64 T, %1; cvt.u32.u64 %0, T; }"
        : "=r"(a) : "l"(p));
    return a;
}
__device__ __forceinline__ void ldsm4(uint32_t addr, uint32_t r[4]) {
    asm volatile("ldmatrix.sync.aligned.m8n8.x4.shared.b16 {%0,%1,%2,%3}, [%4];"
                 : "=r"(r[0]), "=r"(r[1]), "=r"(r[2]), "=r"(r[3]) : "r"(addr));
}
__device__ __forceinline__ void mma_f16(float c[4], const uint32_t a[4],
                                        uint32_t b0, uint32_t b1) {
    asm volatile(
        "mma.sync.aligned.m16n8k16.row.col.f32.f16.f16.f32 "
        "{%0,%1,%2,%3}, {%4,%5,%6,%7}, {%8,%9}, {%0,%1,%2,%3};"
        : "+f"(c[0]), "+f"(c[1]), "+f"(c[2]), "+f"(c[3])
        : "r"(a[0]), "r"(a[1]), "r"(a[2]), "r"(a[3]), "r"(b0), "r"(b1));
}
__device__ __forceinline__ void split16(float a, __half& hi, __half& lo) {
    hi = __float2half_rn(a);
    lo = __float2half_rn((a - __half2float(hi)) * LO_S);
}

// ---------------------------------------------------------------------------
// prep: warp-per-code norms + zero counts + reset done counter
__global__ void prep_kernel(const float* __restrict__ cb) {
    const int code = blockIdx.x * 8 + (threadIdx.x >> 5);
    const int lane = threadIdx.x & 31;
    const float* row = cb + code * C_DIM;
    float s = 0.f;
    #pragma unroll
    for (int c = lane; c < C_DIM; c += 32) { float v = row[c]; s += v * v; }
    #pragma unroll
    for (int off = 16; off > 0; off >>= 1)
        s += __shfl_down_sync(0xffffffffu, s, off);
    if (lane == 0) {
        g_norms[code]  = s;
        g_counts[code] = 0;
        if (code == 0) g_done = 0;
    }
}

// ---------------------------------------------------------------------------
// R12 argmin with interleaved-B smem layout (R8-proven addressing).
// CTA: 128 tokens x all 1024 codes (16 chunks of 64).
// 8 warps = 4 token-groups x 2 code-groups; warp tile = 32 tok x 32 codes.
__global__ __launch_bounds__(256, 1)
void argmin_kernel(const float* __restrict__ z, const float* __restrict__ cb) {
    extern __shared__ char smem[];
    const uint32_t sb = smem_u32(smem);
    float* ns    = (float*)(smem + NS_OFF);
    float* candv = (float*)(smem + CV_OFF);
    int*   candi = (int*)(smem + CI_OFF);

    const int tid  = threadIdx.x;
    const int warp = tid >> 5;
    const int lane = tid & 31;
    const int tg   = warp & 3;
    const int cg   = warp >> 2;
    const int g    = lane >> 2;
    const int t    = lane & 3;
    const int l15  = lane & 15;

    const int n0  = blockIdx.x * MT;
    const int b   = n0 >> 10;
    const int hw0 = n0 & 1023;
    const float* zb = z + (size_t)b * (C_DIM * HW_DIM) + hw0;
    const float4* cb4 = (const float4*)cb;

    // stage A (128 tok x 256 c) as fp16 hi/lo, coalesced over tokens
    for (int it = 0; it < 128; it++) {
        int i  = it * 256 + tid;
        int tk = i & 127;
        int c  = i >> 7;
        float a = zb[(size_t)c * HW_DIM + tk];
        __half hi, lo;
        split16(a, hi, lo);
        *(__half*)(smem + AH_OFF + tk * ROWB + c * 2) = hi;
        *(__half*)(smem + AL_OFF + tk * ROWB + c * 2) = lo;
    }

    const uint32_t aH = sb + AH_OFF + (uint32_t)((tg * 32 + l15) * ROWB + (lane >> 4) * 16);
    const uint32_t aL = aH + (uint32_t)(AL_OFF - AH_OFF);
    // B addressing (R8-proven): row = code within chunk, 1024B interleaved,
    // XOR-swizzled at 16B granularity by (code & 7).
    const int bcode = lane & 7;
    const int bgrp  = lane >> 3;     // 0..3 -> [bh k0-7][bl k0-7][bh k8-15][bl k8-15]
    uint32_t brow[4];
    #pragma unroll
    for (int nb = 0; nb < 4; nb++)
        brow[nb] = sb + BI_OFF + (uint32_t)((cg * 32 + nb * 8 + bcode) * 1024);

    float bestv4[4];
    int   besti4[4];
    #pragma unroll
    for (int s = 0; s < 4; s++) { bestv4[s] = 3.4e38f; besti4[s] = 0; }

    for (int ch = 0; ch < CHUNKS; ch++) {
        const int k0c = ch * NCH;
        __syncthreads();   // protect B from previous chunk's readers
        // stage B chunk (64 codes x 256 c) fp16 hi/lo into interleaved layout
        #pragma unroll
        for (int it = 0; it < 16; it++) {
            int i    = it * 256 + tid;
            int code = i >> 6;
            int j4   = i & 63;
            float4 v = cb4[(size_t)(k0c + code) * 64 + j4];
            __half h0, l0, h1, l1, h2, l2, h3, l3;
            split16(v.x, h0, l0); split16(v.y, h1, l1);
            split16(v.z, h2, l2); split16(v.w, h3, l3);
            __half2 hA = __halves2half2(h0, h1), hB = __halves2half2(h2, h3);
            __half2 lA = __halves2half2(l0, l1), lB = __halves2half2(l2, l3);
            // interleaved: 8-k block kb = j4>>1; hi seg = 2kb, lo seg = 2kb+1,
            // each XOR-swizzled by (code & 7); h = j4&1 selects 8B half of seg.
            int kb = j4 >> 1;
            int h  = j4 & 1;
            int c7 = code & 7;
            uint32_t base = (uint32_t)(code * 1024);
            uint32_t offH = base + (uint32_t)((((2 * kb)     ^ c7) << 4) + h * 8);
            uint32_t offL = base + (uint32_t)((((2 * kb + 1) ^ c7) << 4) + h * 8);
            *(uint2*)(smem + BI_OFF + offH) = make_uint2(*(uint32_t*)&hA, *(uint32_t*)&hB);
            *(uint2*)(smem + BI_OFF + offL) = make_uint2(*(uint32_t*)&lA, *(uint32_t*)&lB);
        }
        if (tid < NCH) ns[tid] = g_norms[k0c + tid];
        __syncthreads();

        float hh[2][4][4], md[2][4][4];
        #pragma unroll
        for (int mt = 0; mt < 2; mt++)
            #pragma unroll
            for (int nb = 0; nb < 4; nb++)
                #pragma unroll
                for (int q = 0; q < 4; q++) { hh[mt][nb][q] = 0.f; md[mt][nb][q] = 0.f; }

        #pragma unroll 4
        for (int ks = 0; ks < KSTEPS; ks++) {
            uint32_t ah[2][4], al[2][4];
            #pragma unroll
            for (int mt = 0; mt < 2; mt++) {
                ldsm4(aH + (uint32_t)(mt * 16 * ROWB + ks * 32), ah[mt]);
                ldsm4(aL + (uint32_t)(mt * 16 * ROWB + ks * 32), al[mt]);
            }
            const uint32_t koff = (uint32_t)(((4 * ks + bgrp) ^ bcode) << 4);
            #pragma unroll
            for (int nb = 0; nb < 4; nb++) {
                uint32_t bb[4];
                ldsm4(brow[nb] + koff, bb);
                #pragma unroll
                for (int mt = 0; mt < 2; mt++) {
                    mma_f16(hh[mt][nb], ah[mt], bb[0], bb[2]);  // ah*bh
                    mma_f16(md[mt][nb], ah[mt], bb[1], bb[3]);  // ah*bl
                    mma_f16(md[mt][nb], al[mt], bb[0], bb[2]);  // al*bh
                }
            }
        }

        // epilogue: dist = |e|^2 - 2 (hh + md/2048)
        #pragma unroll
        for (int nb = 0; nb < 4; nb++) {
            int cl = cg * 32 + nb * 8 + 2 * t;
            float nk0 = ns[cl];
            float nk1 = ns[cl + 1];
            int code0 = k0c + cl;
            #pragma unroll
            for (int mt = 0; mt < 2; mt++) {
                float d00 = nk0 - 2.f * (hh[mt][nb][0] + md[mt][nb][0] * LO_IS);
                float d01 = nk1 - 2.f * (hh[mt][nb][1] + md[mt][nb][1] * LO_IS);
                float d10 = nk0 - 2.f * (hh[mt][nb][2] + md[mt][nb][2] * LO_IS);
                float d11 = nk1 - 2.f * (hh[mt][nb][3] + md[mt][nb][3] * LO_IS);
                int s0 = mt * 2, s1 = mt * 2 + 1;
                if (d00 < bestv4[s0]) { bestv4[s0] = d00; besti4[s0] = code0; }
                if (d01 < bestv4[s0]) { bestv4[s0] = d01; besti4[s0] = code0 + 1; }
                if (d10 < bestv4[s1]) { bestv4[s1] = d10; besti4[s1] = code0; }
                if (d11 < bestv4[s1]) { bestv4[s1] = d11; besti4[s1] = code0 + 1; }
            }
        }
    }

    // lane-reduce across t (lanes 4g..4g+3 share a token row)
    #pragma unroll
    for (int s = 0; s < 4; s++) {
        #pragma unroll
        for (int m = 1; m <= 2; m <<= 1) {
            float v2 = __shfl_xor_sync(0xffffffffu, bestv4[s], m);
            int   i2 = __shfl_xor_sync(0xffffffffu, besti4[s], m);
            if (v2 < bestv4[s] || (v2 == bestv4[s] && i2 < besti4[s])) {
                bestv4[s] = v2; besti4[s] = i2;
            }
        }
    }
    if (t == 0) {
        #pragma unroll
        for (int s = 0; s < 4; s++) {
            int mt = s >> 1, h = s & 1;
            int tok = tg * 32 + mt * 16 + h * 8 + g;
            candv[tok * 2 + cg] = bestv4[s];
            candi[tok * 2 + cg] = besti4[s];
        }
    }
    __syncthreads();
    if (tid < MT) {
        float v0 = candv[tid * 2], v1 = candv[tid * 2 + 1];
        int   i0 = candi[tid * 2], i1 = candi[tid * 2 + 1];
        int bi;
        if (v1 < v0 || (v1 == v0 && i1 < i0)) bi = i1; else bi = i0;
        g_idx[n0 + tid] = bi;
        atomicAdd(&g_counts[bi], 1);
    }
}

// ---------------------------------------------------------------------------
// gather + fused finalize: 1024 blocks, 32 tokens/block, 8 threads/token.
__global__ __launch_bounds__(256)
void gather_loss_kernel(const float* __restrict__ z,
                        const float* __restrict__ cb,
                        float* __restrict__ out, int out_size) {
    __shared__ float red[256];
    __shared__ float red2[256];
    __shared__ bool  amLast;
    const int tid = threadIdx.x;
    const int tok = blockIdx.x * 32 + (tid & 31);
    const int cc  = tid >> 5;
    const int k   = g_idx[tok];
    const int b   = tok >> 10;
    const int hw  = tok & 1023;
    const float4* c4p = (const float4*)cb + (size_t)k * 64 + cc * 8;
    const size_t base = (size_t)b * (C_DIM * HW_DIM) + (size_t)cc * 32 * HW_DIM + hw;
    const float* zp = z + base;
    float* op = out + base;
    float s = 0.f;
    #pragma unroll
    for (int j = 0; j < 8; j++) {
        float4 e = c4p[j];
        int c = j * 4;
        float d0 = e.x - zp[(c + 0) * HW_DIM];
        float d1 = e.y - zp[(c + 1) * HW_DIM];
        float d2 = e.z - zp[(c + 2) * HW_DIM];
        float d3 = e.w - zp[(c + 3) * HW_DIM];
        s += d0 * d0 + d1 * d1 + d2 * d2 + d3 * d3;
        op[(c + 0) * HW_DIM] = e.x;
        op[(c + 1) * HW_DIM] = e.y;
        op[(c + 2) * HW_DIM] = e.z;
        op[(c + 3) * HW_DIM] = e.w;
    }
    red[tid] = s;
    __syncthreads();
    for (int off = 128; off > 0; off >>= 1) {
        if (tid < off) red[tid] += red[tid + off];
        __syncthreads();
    }
    if (tid == 0) {
        g_partials[blockIdx.x] = red[0];
        __threadfence();
        amLast = (atomicAdd(&g_done, 1) == GL_BLOCKS - 1);
    }
    __syncthreads();

    if (amLast) {
        float ls = g_partials[tid] + g_partials[tid + 256]
                 + g_partials[tid + 512] + g_partials[tid + 768];
        float en = 0.f;
        #pragma unroll
        for (int j = 0; j < 4; j++) {
            float p  = (float)g_counts[tid * 4 + j] * (1.0f / (float)N_TOK);
            float pc = fmaxf(p, 1e-10f);
            en += pc * logf(pc);
        }
        red[tid]  = ls;
        red2[tid] = en;
        __syncthreads();
        for (int off = 128; off > 0; off >>= 1) {
            if (tid < off) { red[tid] += red[tid + off]; red2[tid] += red2[tid + off]; }
            __syncthreads();
        }
        if (tid == 0) {
            float mse = red[0] * (1.0f / (float)Z_ELEMS);
            if (out_size >= Z_ELEMS + 1) out[Z_ELEMS]     = mse * (1.0f + BETA_F);
            if (out_size >= Z_ELEMS + 2) out[Z_ELEMS + 1] = expf(-red2[0]);
        }
    }
}

// ---------------------------------------------------------------------------
extern "C" void kernel_launch(void* const* d_in, const int* in_sizes, int n_in,
                              void* d_out, int out_size) {
    const float* z  = (const float*)d_in[0];
    const float* cb = (const float*)d_in[1];
    float* out = (float*)d_out;

    cudaFuncSetAttribute(argmin_kernel,
                         cudaFuncAttributeMaxDynamicSharedMemorySize, SMEM_TOTAL);

    prep_kernel<<<K_CODES / 8, 256>>>(cb);
    argmin_kernel<<<N_TOK / MT, 256, SMEM_TOTAL>>>(z, cb);
    gather_loss_kernel<<<GL_BLOCKS, 256>>>(z, cb, out, out_size);
}

// round 17
// speedup vs baseline: 1.2383x; 1.0919x over previous
#include <cuda_runtime.h>
#include <cuda_fp16.h>
#include <math.h>
#include <stdint.h>

// Shapes (fixed)
#define HW_DIM  1024
#define C_DIM   256
#define N_TOK   32768
#define K_CODES 1024
#define Z_ELEMS 8388608
#define BETA_F  0.25f

// tiling (R4/R13-identical)
#define MT      128            // tokens per CTA
#define NCH     64             // codes per chunk
#define CHUNKS  (K_CODES / NCH)
#define KSTEPS  (C_DIM / 16)   // 16

// fp16 split scale (proven)
#define LO_S    2048.0f
#define LO_IS   4.8828125e-4f

// smem layout (bytes)
#define ROWB    528
#define AH_OFF  0               // 128*528 = 67584
#define AL_OFF  67584           // -> 135168
#define BH_OFF  135168          // 64*528 = 33792 -> 168960
#define BL_OFF  168960          // -> 202752
#define NS_OFF  202752          // 1024 floats -> 206848
#define CV_OFF  206848          // 128*2 floats -> 207872
#define CI_OFF  207872          // 128*2 ints -> 208896
#define SMEM_TOTAL 208896

#define GL_BLOCKS 1024          // gather: 32 tokens/block, 8 threads/token

static __device__ int   g_idx[N_TOK];
static __device__ int   g_counts[K_CODES];
static __device__ float g_norms[K_CODES];
static __device__ float g_partials[GL_BLOCKS];
static __device__ int   g_done;

// ---------------------------------------------------------------------------
__device__ __forceinline__ uint32_t smem_u32(const void* p) {
    uint32_t a;
    asm("{ .reg .u64 T; cvta.to.shared.u64 T, %1; cvt.u32.u64 %0, T; }"
        : "=r"(a) : "l"(p));
    return a;
}
__device__ __forceinline__ void ldsm4(uint32_t addr, uint32_t r[4]) {
    asm volatile("ldmatrix.sync.aligned.m8n8.x4.shared.b16 {%0,%1,%2,%3}, [%4];"
                 : "=r"(r[0]), "=r"(r[1]), "=r"(r[2]), "=r"(r[3]) : "r"(addr));
}
__device__ __forceinline__ void ldsm2(uint32_t addr, uint32_t r[2]) {
    asm volatile("ldmatrix.sync.aligned.m8n8.x2.shared.b16 {%0,%1}, [%2];"
                 : "=r"(r[0]), "=r"(r[1]) : "r"(addr));
}
__device__ __forceinline__ void mma_f16(float c[4], const uint32_t a[4],
                                        uint32_t b0, uint32_t b1) {
    asm volatile(
        "mma.sync.aligned.m16n8k16.row.col.f32.f16.f16.f32 "
        "{%0,%1,%2,%3}, {%4,%5,%6,%7}, {%8,%9}, {%0,%1,%2,%3};"
        : "+f"(c[0]), "+f"(c[1]), "+f"(c[2]), "+f"(c[3])
        : "r"(a[0]), "r"(a[1]), "r"(a[2]), "r"(a[3]), "r"(b0), "r"(b1));
}
__device__ __forceinline__ void split16(float a, __half& hi, __half& lo) {
    hi = __float2half_rn(a);
    lo = __float2half_rn((a - __half2float(hi)) * LO_S);
}

// ---------------------------------------------------------------------------
// prep: warp-per-code norms + zero counts + reset done counter
__global__ void prep_kernel(const float* __restrict__ cb) {
    const int code = blockIdx.x * 8 + (threadIdx.x >> 5);
    const int lane = threadIdx.x & 31;
    const float* row = cb + code * C_DIM;
    float s = 0.f;
    #pragma unroll
    for (int c = lane; c < C_DIM; c += 32) { float v = row[c]; s += v * v; }
    #pragma unroll
    for (int off = 16; off > 0; off >>= 1)
        s += __shfl_down_sync(0xffffffffu, s, off);
    if (lane == 0) {
        g_norms[code]  = s;
        g_counts[code] = 0;
        if (code == 0) g_done = 0;
    }
}

// ---------------------------------------------------------------------------
// R13 argmin kernel; A staged via float2, norms hoisted once.
// CTA: 128 tokens x all 1024 codes (16 chunks of 64).
// 8 warps = 4 token-groups x 2 code-groups; warp tile = 32 tok x 32 codes.
__global__ __launch_bounds__(256, 1)
void argmin_kernel(const float* __restrict__ z, const float* __restrict__ cb) {
    extern __shared__ char smem[];
    const uint32_t sb = smem_u32(smem);
    float* ns    = (float*)(smem + NS_OFF);
    float* candv = (float*)(smem + CV_OFF);
    int*   candi = (int*)(smem + CI_OFF);

    const int tid  = threadIdx.x;
    const int warp = tid >> 5;
    const int lane = tid & 31;
    const int tg   = warp & 3;
    const int cg   = warp >> 2;
    const int g    = lane >> 2;
    const int t    = lane & 3;
    const int l15  = lane & 15;

    const int n0  = blockIdx.x * MT;
    const int b   = n0 >> 10;
    const int hw0 = n0 & 1023;
    const float* zb = z + (size_t)b * (C_DIM * HW_DIM) + hw0;
    const float4* cb4 = (const float4*)cb;

    // stage A (128 tok x 256 c) as fp16 hi/lo, float2 loads over token pairs
    #pragma unroll 4
    for (int it = 0; it < 64; it++) {
        int p   = it * 256 + tid;          // pair index: 16384 pairs
        int tk2 = (p & 63) * 2;
        int c   = p >> 6;
        float2 a2 = *(const float2*)(zb + (size_t)c * HW_DIM + tk2);
        __half h0, l0, h1, l1;
        split16(a2.x, h0, l0);
        split16(a2.y, h1, l1);
        *(__half*)(smem + AH_OFF + tk2 * ROWB + c * 2)       = h0;
        *(__half*)(smem + AL_OFF + tk2 * ROWB + c * 2)       = l0;
        *(__half*)(smem + AH_OFF + (tk2 + 1) * ROWB + c * 2) = h1;
        *(__half*)(smem + AL_OFF + (tk2 + 1) * ROWB + c * 2) = l1;
    }
    // hoist all 1024 norms into smem once
    #pragma unroll
    for (int it = 0; it < 4; it++) ns[it * 256 + tid] = g_norms[it * 256 + tid];

    const uint32_t aH  = sb + AH_OFF + (uint32_t)((tg * 32 + l15) * ROWB + (lane >> 4) * 16);
    const uint32_t aL  = aH + (uint32_t)(AL_OFF - AH_OFF);
    const uint32_t bHb = sb + BH_OFF + (uint32_t)((cg * 32 + (l15 & 7)) * ROWB + (l15 >> 3) * 16);
    const uint32_t bLb = bHb + (uint32_t)(BL_OFF - BH_OFF);

    float bestv4[4];
    int   besti4[4];
    #pragma unroll
    for (int s = 0; s < 4; s++) { bestv4[s] = 3.4e38f; besti4[s] = 0; }

    for (int ch = 0; ch < CHUNKS; ch++) {
        const int k0c = ch * NCH;
        __syncthreads();   // protect B from previous chunk's readers
        // stage B chunk (64 codes x 256 c) fp16 hi/lo (R13-identical)
        #pragma unroll
        for (int it = 0; it < 16; it++) {
            int i    = it * 256 + tid;
            int code = i >> 6;
            int j4   = i & 63;
            float4 v = cb4[(size_t)(k0c + code) * 64 + j4];
            __half h0, l0, h1, l1, h2, l2, h3, l3;
            split16(v.x, h0, l0); split16(v.y, h1, l1);
            split16(v.z, h2, l2); split16(v.w, h3, l3);
            __half2 hA = __halves2half2(h0, h1), hB = __halves2half2(h2, h3);
            __half2 lA = __halves2half2(l0, l1), lB = __halves2half2(l2, l3);
            uint32_t off = (uint32_t)(code * ROWB + j4 * 8);
            *(uint2*)(smem + BH_OFF + off) = make_uint2(*(uint32_t*)&hA, *(uint32_t*)&hB);
            *(uint2*)(smem + BL_OFF + off) = make_uint2(*(uint32_t*)&lA, *(uint32_t*)&lB);
        }
        __syncthreads();

        float hh[2][4][4], md[2][4][4];
        #pragma unroll
        for (int mt = 0; mt < 2; mt++)
            #pragma unroll
            for (int nb = 0; nb < 4; nb++)
                #pragma unroll
                for (int q = 0; q < 4; q++) { hh[mt][nb][q] = 0.f; md[mt][nb][q] = 0.f; }

        #pragma unroll 4
        for (int ks = 0; ks < KSTEPS; ks++) {
            uint32_t ah[2][4], al[2][4];
            #pragma unroll
            for (int mt = 0; mt < 2; mt++) {
                ldsm4(aH + (uint32_t)(mt * 16 * ROWB + ks * 32), ah[mt]);
                ldsm4(aL + (uint32_t)(mt * 16 * ROWB + ks * 32), al[mt]);
            }
            #pragma unroll
            for (int nb = 0; nb < 4; nb++) {
                uint32_t bh[2], bl[2];
                ldsm2(bHb + (uint32_t)(nb * 8 * ROWB + ks * 32), bh);
                ldsm2(bLb + (uint32_t)(nb * 8 * ROWB + ks * 32), bl);
                #pragma unroll
                for (int mt = 0; mt < 2; mt++) {
                    mma_f16(hh[mt][nb], ah[mt], bh[0], bh[1]);
                    mma_f16(md[mt][nb], ah[mt], bl[0], bl[1]);
                    mma_f16(md[mt][nb], al[mt], bh[0], bh[1]);
                }
            }
        }

        // epilogue: dist = |e|^2 - 2 (hh + md/2048); global-indexed norms
        #pragma unroll
        for (int nb = 0; nb < 4; nb++) {
            int cl = cg * 32 + nb * 8 + 2 * t;
            int code0 = k0c + cl;
            float nk0 = ns[code0];
            float nk1 = ns[code0 + 1];
            #pragma unroll
            for (int mt = 0; mt < 2; mt++) {
                float d00 = nk0 - 2.f * (hh[mt][nb][0] + md[mt][nb][0] * LO_IS);
                float d01 = nk1 - 2.f * (hh[mt][nb][1] + md[mt][nb][1] * LO_IS);
                float d10 = nk0 - 2.f * (hh[mt][nb][2] + md[mt][nb][2] * LO_IS);
                float d11 = nk1 - 2.f * (hh[mt][nb][3] + md[mt][nb][3] * LO_IS);
                int s0 = mt * 2, s1 = mt * 2 + 1;
                if (d00 < bestv4[s0]) { bestv4[s0] = d00; besti4[s0] = code0; }
                if (d01 < bestv4[s0]) { bestv4[s0] = d01; besti4[s0] = code0 + 1; }
                if (d10 < bestv4[s1]) { bestv4[s1] = d10; besti4[s1] = code0; }
                if (d11 < bestv4[s1]) { bestv4[s1] = d11; besti4[s1] = code0 + 1; }
            }
        }
    }

    // lane-reduce across t (lanes 4g..4g+3 share a token row)
    #pragma unroll
    for (int s = 0; s < 4; s++) {
        #pragma unroll
        for (int m = 1; m <= 2; m <<= 1) {
            float v2 = __shfl_xor_sync(0xffffffffu, bestv4[s], m);
            int   i2 = __shfl_xor_sync(0xffffffffu, besti4[s], m);
            if (v2 < bestv4[s] || (v2 == bestv4[s] && i2 < besti4[s])) {
                bestv4[s] = v2; besti4[s] = i2;
            }
        }
    }
    if (t == 0) {
        #pragma unroll
        for (int s = 0; s < 4; s++) {
            int mt = s >> 1, h = s & 1;
            int tok = tg * 32 + mt * 16 + h * 8 + g;
            candv[tok * 2 + cg] = bestv4[s];
            candi[tok * 2 + cg] = besti4[s];
        }
    }
    __syncthreads();
    if (tid < MT) {
        float v0 = candv[tid * 2], v1 = candv[tid * 2 + 1];
        int   i0 = candi[tid * 2], i1 = candi[tid * 2 + 1];
        int bi;
        if (v1 < v0 || (v1 == v0 && i1 < i0)) bi = i1; else bi = i0;
        g_idx[n0 + tid] = bi;
        atomicAdd(&g_counts[bi], 1);
    }
}

// ---------------------------------------------------------------------------
// gather + fused finalize: 1024 blocks, 32 tokens/block, 8 threads/token.
__global__ __launch_bounds__(256)
void gather_loss_kernel(const float* __restrict__ z,
                        const float* __restrict__ cb,
                        float* __restrict__ out, int out_size) {
    __shared__ float red[256];
    __shared__ float red2[256];
    __shared__ bool  amLast;
    const int tid = threadIdx.x;
    const int tok = blockIdx.x * 32 + (tid & 31);
    const int cc  = tid >> 5;
    const int k   = g_idx[tok];
    const int b   = tok >> 10;
    const int hw  = tok & 1023;
    const float4* c4p = (const float4*)cb + (size_t)k * 64 + cc * 8;
    const size_t base = (size_t)b * (C_DIM * HW_DIM) + (size_t)cc * 32 * HW_DIM + hw;
    const float* zp = z + base;
    float* op = out + base;
    float s = 0.f;
    #pragma unroll
    for (int j = 0; j < 8; j++) {
        float4 e = c4p[j];
        int c = j * 4;
        float d0 = e.x - zp[(c + 0) * HW_DIM];
        float d1 = e.y - zp[(c + 1) * HW_DIM];
        float d2 = e.z - zp[(c + 2) * HW_DIM];
        float d3 = e.w - zp[(c + 3) * HW_DIM];
        s += d0 * d0 + d1 * d1 + d2 * d2 + d3 * d3;
        op[(c + 0) * HW_DIM] = e.x;
        op[(c + 1) * HW_DIM] = e.y;
        op[(c + 2) * HW_DIM] = e.z;
        op[(c + 3) * HW_DIM] = e.w;
    }
    red[tid] = s;
    __syncthreads();
    for (int off = 128; off > 0; off >>= 1) {
        if (tid < off) red[tid] += red[tid + off];
        __syncthreads();
    }
    if (tid == 0) {
        g_partials[blockIdx.x] = red[0];
        __threadfence();
        amLast = (atomicAdd(&g_done, 1) == GL_BLOCKS - 1);
    }
    __syncthreads();

    if (amLast) {
        float ls = g_partials[tid] + g_partials[tid + 256]
                 + g_partials[tid + 512] + g_partials[tid + 768];
        float en = 0.f;
        #pragma unroll
        for (int j = 0; j < 4; j++) {
            float p  = (float)g_counts[tid * 4 + j] * (1.0f / (float)N_TOK);
            float pc = fmaxf(p, 1e-10f);
            en += pc * logf(pc);
        }
        red[tid]  = ls;
        red2[tid] = en;
        __syncthreads();
        for (int off = 128; off > 0; off >>= 1) {
            if (tid < off) { red[tid] += red[tid + off]; red2[tid] += red2[tid + off]; }
            __syncthreads();
        }
        if (tid == 0) {
            float mse = red[0] * (1.0f / (float)Z_ELEMS);
            if (out_size >= Z_ELEMS + 1) out[Z_ELEMS]     = mse * (1.0f + BETA_F);
            if (out_size >= Z_ELEMS + 2) out[Z_ELEMS + 1] = expf(-red2[0]);
        }
    }
}

// ---------------------------------------------------------------------------
extern "C" void kernel_launch(void* const* d_in, const int* in_sizes, int n_in,
                              void* d_out, int out_size) {
    const float* z  = (const float*)d_in[0];
    const float* cb = (const float*)d_in[1];
    float* out = (float*)d_out;

    cudaFuncSetAttribute(argmin_kernel,
                         cudaFuncAttributeMaxDynamicSharedMemorySize, SMEM_TOTAL);

    prep_kernel<<<K_CODES / 8, 256>>>(cb);
    argmin_kernel<<<N_TOK / MT, 256, SMEM_TOTAL>>>(z, cb);
    gather_loss_kernel<<<GL_BLOCKS, 256>>>(z, cb, out, out_size);
}